// round 13
// baseline (speedup 1.0000x reference)
#include <cuda_runtime.h>
#include <math.h>

#define N 320
#define D 128
#define NMAT 3
#define RHO_C 10.0f
#define MARGIN_C 0.2f
#define TAU_C 1.3f
#define SEMIHARD_THRESH_C 0.01f
#define EPS_C 1e-12f
#define NTRI  210                // 20*21/2 lower-triangle 16x16 tiles
#define NCH   4                  // k chunks
#define KCH   80                 // k-chunk size (N/4)

// ---------------- device scratch (no allocations allowed) ----------------
__device__ float  g_d[NMAT][N][N];   // pairwise distances per matrix
__device__ float2 g_mm[NCH][N][N];   // per-chunk (maxs, minn) partials
__device__ float  g_pden[N];         // per-i row sums of pw
__device__ float  g_pnum[N];         // per-i sums of pos*pair_w
__device__ unsigned int g_cnt_i[N];  // per-i chunk tickets
__device__ unsigned int g_counter;   // global ticket for fused final

// ---------------- kernel 1: distances; 630 blocks = 210 tiles x 3 mats ------
#define PADW 132
__global__ void __launch_bounds__(256) k_dist(const float* __restrict__ src,
                                              const float* __restrict__ emb) {
    int b  = blockIdx.x;
    int m  = b / NTRI;
    int bt = b - m * NTRI;
    int bi = (int)((sqrtf(8.0f * (float)bt + 1.0f) - 1.0f) * 0.5f);
    while ((bi + 1) * (bi + 2) / 2 <= bt) bi++;
    while (bi * (bi + 1) / 2 > bt) bi--;
    int bj = bt - bi * (bi + 1) / 2;
    int i0 = bi * 16, j0 = bj * 16;

    __shared__ float Ai[16][PADW];
    __shared__ float Aj[16][PADW];
    __shared__ float s_sq[32];
    __shared__ float s_ri[32];

    int t  = threadIdx.x;
    int tx = t & 15, ty = t >> 4;
    int lane = t & 31, warp = t >> 5;
    int i = i0 + ty, j = j0 + tx;

    if (b == 0) {                       // reset tickets (precedes k_tripart)
        if (t == 0) g_counter = 0;
        for (int e = t; e < N; e += 256) g_cnt_i[e] = 0;
    }

    const float* base = (m < 2) ? (src + (size_t)m * N * D) : emb;
    for (int e = t; e < 16 * 32; e += 256) {
        int r = e >> 5, c4 = e & 31;
        *(float4*)&Ai[r][c4 * 4] = ((const float4*)(base + (size_t)(i0 + r) * D))[c4];
        *(float4*)&Aj[r][c4 * 4] = ((const float4*)(base + (size_t)(j0 + r) * D))[c4];
    }
    __syncthreads();

    #pragma unroll
    for (int rr = 0; rr < 4; rr++) {
        int row = warp * 4 + rr;
        const float* rp = (row < 16) ? &Ai[row][0] : &Aj[row - 16][0];
        float4 x = ((const float4*)rp)[lane];
        float ssum = x.x * x.x + x.y * x.y + x.z * x.z + x.w * x.w;
        #pragma unroll
        for (int o = 16; o > 0; o >>= 1) ssum += __shfl_xor_sync(0xffffffffu, ssum, o);
        if (lane == 0) {
            float rn = 1.0f / fmaxf(sqrtf(ssum), EPS_C);
            s_sq[row] = ssum * (rn * rn);
            s_ri[row] = rn;
        }
    }
    __syncthreads();

    const float4* ai = (const float4*)&Ai[ty][0];
    const float4* aj = (const float4*)&Aj[tx][0];
    float d0 = 0.f, d1 = 0.f, d2a = 0.f, d3 = 0.f;
    #pragma unroll 8
    for (int c = 0; c < 32; c++) {
        float4 a = ai[c];
        float4 bb = aj[c];
        d0  += a.x * bb.x;
        d1  += a.y * bb.y;
        d2a += a.z * bb.z;
        d3  += a.w * bb.w;
    }
    float dot = (d0 + d1) + (d2a + d3);
    float rij = s_ri[ty] * s_ri[16 + tx];
    float dd  = s_sq[ty] + s_sq[16 + tx] - 2.0f * (dot * rij);
    float d   = sqrtf(fmaxf(dd, 0.0f) + EPS_C);
    g_d[m][i][j] = d;
    if (bi != bj) g_d[m][j][i] = d;    // bitwise symmetric by construction
}

// ---------------- kernel 2: 4-way split-k triplet (pure scalar) -------------
// grid: 1280 blocks (i = bx>>2, kc = bx&3), 320 threads (one per j).
// Scalar loop at the 7-issue/k semantic floor; one interleaved (-dk, bk)
// stream read as float4 (2 k's per LDS.128). No f32x2 pack/unpack movs.
__global__ void __launch_bounds__(N) k_tripart(float* __restrict__ out) {
    int i  = blockIdx.x >> 2;
    int kc = blockIdx.x & 3;
    int t  = threadIdx.x;          // j

    __shared__ __align__(16) float2 s2[KCH];   // (-d_emb[i][k], 1-pw[i][k])

    // prologue: own-column pw for every thread; chunk columns for t < KCH
    float d0j = g_d[0][i][t];
    float d1j = g_d[1][i][t];
    float dij = g_d[2][i][t];
    float pwij = 1.0f / (1.0f + expf(-RHO_C * (TAU_C - 0.5f * (d0j + d1j))));
    if (t < KCH) {
        int c = kc * KCH + t;
        float a0 = g_d[0][i][c];
        float a1 = g_d[1][i][c];
        float de = g_d[2][i][c];
        float pwc = 1.0f / (1.0f + expf(-RHO_C * (TAU_C - 0.5f * (a0 + a1))));
        s2[t] = make_float2(-de, 1.0f - pwc);
    }
    __syncthreads();

    float nrpw = -(RHO_C * pwij);

    float mx0 = 0.0f, mx1 = 0.0f;
    float mn0 = 1e30f, mn1 = 1e30f;

    const float4* p4 = (const float4*)s2;      // (nd0, bk0, nd1, bk1)

    // m = fl(M + fl(dij + (-dk))) == fl(M - diff): reference rounding exactly.
    // k==j -> inner fl == 0 exactly -> m == 0.2f exactly -> semihard.
    // Classify on m <= MARGIN (NOT on dk >= dij: differs in a ulp sliver).
    #pragma unroll 8
    for (int q = 0; q < KCH / 2; q++) {
        float4 v = p4[q];
        {
            float tt = dij + v.x;
            float m  = MARGIN_C + tt;
            float vs = m * v.y;
            float vh = fmaf(nrpw, v.y, m);
            if (m <= MARGIN_C) mx0 = fmaxf(mx0, vs); else mn0 = fminf(mn0, vh);
        }
        {
            float tt = dij + v.z;
            float m  = MARGIN_C + tt;
            float vs = m * v.w;
            float vh = fmaf(nrpw, v.w, m);
            if (m <= MARGIN_C) mx1 = fmaxf(mx1, vs); else mn1 = fminf(mn1, vh);
        }
    }
    float maxs = fmaxf(mx0, mx1);      // assoc+comm: bit-exact combine
    float minn = fminf(mn0, mn1);

    __stcg(&g_mm[kc][i][t], make_float2(maxs, minn));
    __threadfence();

    // per-i ticket: 4th chunk block to finish combines row i
    __shared__ bool win_i;
    if (t == 0) win_i = (atomicAdd(&g_cnt_i[i], 1u) == (unsigned)(NCH - 1));
    __syncthreads();
    if (!win_i) return;

    float2 c0 = __ldcg(&g_mm[0][i][t]);
    float2 c1 = __ldcg(&g_mm[1][i][t]);
    float2 c2 = __ldcg(&g_mm[2][i][t]);
    float2 c3 = __ldcg(&g_mm[3][i][t]);
    float mx = fmaxf(fmaxf(c0.x, c1.x), fmaxf(c2.x, c3.x));
    float mn = fminf(fminf(c0.y, c1.y), fminf(c2.y, c3.y));
    float psh = pwij * mx;                          // pos_semihard
    float ph  = (mn < 0.0f) ? (mn + RHO_C) : 0.0f;
    float pos = psh + ((psh <= SEMIHARD_THRESH_C) ? ph : 0.0f);
    float contrib = pos * pwij;

    // deterministic dual block reduction: contrib (num) and pwij (den)
    float v = contrib, w = pwij;
    #pragma unroll
    for (int o = 16; o > 0; o >>= 1) {
        v += __shfl_down_sync(0xffffffffu, v, o);
        w += __shfl_down_sync(0xffffffffu, w, o);
    }
    __shared__ float swn[10], swd[10];
    int lane = t & 31, warp = t >> 5;
    if (lane == 0) { swn[warp] = v; swd[warp] = w; }
    __syncthreads();
    if (warp == 0 && lane == 0) {
        float sn = 0.0f, sd = 0.0f;
        #pragma unroll
        for (int q = 0; q < 10; q++) { sn += swn[q]; sd += swd[q]; }
        g_pnum[i] = sn;
        g_pden[i] = sd;
    }

    // ---- fused final: last winning block sums everything ----
    __threadfence();
    __shared__ bool is_last;
    if (t == 0) is_last = (atomicAdd(&g_counter, 1u) == (unsigned)(N - 1));
    __syncthreads();
    if (!is_last) return;

    float num = __ldcg(&g_pnum[t]);
    float den = __ldcg(&g_pden[t]);
    #pragma unroll
    for (int o = 16; o > 0; o >>= 1) {
        num += __shfl_down_sync(0xffffffffu, num, o);
        den += __shfl_down_sync(0xffffffffu, den, o);
    }
    __shared__ float sn2[10], sd2[10];
    if (lane == 0) { sn2[warp] = num; sd2[warp] = den; }
    __syncthreads();
    if (t == 0) {
        float fn = 0.0f, fd = 0.0f;
        #pragma unroll
        for (int q = 0; q < 10; q++) { fn += sn2[q]; fd += sd2[q]; }
        out[0] = (fd > 0.0f) ? (fn / fmaxf(fd, EPS_C)) : 0.0f;
    }
}

extern "C" void kernel_launch(void* const* d_in, const int* in_sizes, int n_in,
                              void* d_out, int out_size) {
    (void)n_in; (void)out_size;
    const float* src = (const float*)d_in[0];
    const float* emb = (const float*)d_in[1];
    if (n_in >= 2 && in_sizes[0] == N * D && in_sizes[1] == 2 * N * D) {
        const float* tmp = src; src = emb; emb = tmp;
    }
    float* out = (float*)d_out;

    k_dist<<<NMAT * NTRI, 256>>>(src, emb);
    k_tripart<<<NCH * N, N>>>(out);
}